// round 3
// baseline (speedup 1.0000x reference)
#include <cuda_runtime.h>
#include <cuda_bf16.h>
#include <cstddef>

#define NN 100000
#define EE 1600000
#define D_IN 128
#define HID 128
#define D_OUT 64

// ---------------- scratch (device globals; no allocation allowed) ----------
__device__ float g_xl[(size_t)NN * HID];    // x @ W_l1
__device__ float g_xr[(size_t)NN * HID];    // x @ W_r1
__device__ float g_agg[(size_t)NN * HID];   // layer-1 neighbor sum
__device__ float g_h[(size_t)NN * HID];     // relu output of layer 1
__device__ float g_hl[(size_t)NN * D_OUT];  // h @ W_l2
__device__ float g_hr[(size_t)NN * D_OUT];  // h @ W_r2
__device__ float g_agg2[(size_t)NN * D_OUT];// layer-2 neighbor sum
__device__ float g_cnt[NN];                 // in-degree
__device__ int   g_src[EE];                 // converted edge sources
__device__ int   g_dst[EE];                 // converted edge destinations
__device__ int   g_is64;                    // edge_index dtype flag

// ---------------- dtype detection -----------------------------------------
// int32 node ids fit in 17 bits; if the buffer really holds int64, reading it
// as int64 gives values in [0, NN). If it holds int32, an int64 read combines
// two ids -> almost surely >= 2^32 (only zero high-word escapes; require all
// 256 samples in range).
__global__ void detect_kernel(const void* __restrict__ ei_raw) {
    if (threadIdx.x == 0 && blockIdx.x == 0) {
        const long long* e64 = (const long long*)ei_raw;
        int ok = 1;
        for (int i = 0; i < 256; i++) {
            long long v = e64[i];
            if (v < 0 || v >= NN) { ok = 0; break; }
        }
        g_is64 = ok;
    }
}

// ---------------- zero scratch --------------------------------------------
__global__ void zero_kernel() {
    int i = blockIdx.x * blockDim.x + threadIdx.x;
    int stride = gridDim.x * blockDim.x;
    float4 z = make_float4(0.f, 0.f, 0.f, 0.f);
    float4* a1 = reinterpret_cast<float4*>(g_agg);
    float4* a2 = reinterpret_cast<float4*>(g_agg2);
    const int n1 = NN * HID / 4;
    const int n2 = NN * D_OUT / 4;
    for (int idx = i; idx < n1; idx += stride) a1[idx] = z;
    for (int idx = i; idx < n2; idx += stride) a2[idx] = z;
    for (int idx = i; idx < NN; idx += stride) g_cnt[idx] = 0.f;
}

// ---------------- convert edge index + degree count ------------------------
__global__ void convert_kernel(const void* __restrict__ ei_raw) {
    int i = blockIdx.x * blockDim.x + threadIdx.x;
    int stride = gridDim.x * blockDim.x;
    const int is64 = g_is64;
    if (is64) {
        const long long* e64 = (const long long*)ei_raw;
        for (int e = i; e < EE; e += stride) {
            int s = (int)e64[e];
            int d = (int)e64[(size_t)EE + e];
            s = min(max(s, 0), NN - 1);
            d = min(max(d, 0), NN - 1);
            g_src[e] = s;
            g_dst[e] = d;
            atomicAdd(&g_cnt[d], 1.0f);
        }
    } else {
        const int* e32 = (const int*)ei_raw;
        for (int e = i; e < EE; e += stride) {
            int s = e32[e];
            int d = e32[EE + e];
            s = min(max(s, 0), NN - 1);
            d = min(max(d, 0), NN - 1);
            g_src[e] = s;
            g_dst[e] = d;
            atomicAdd(&g_cnt[d], 1.0f);
        }
    }
}

// ---------------- dual GEMM body: C1 = A@B1, C2 = A@B2 (K = 128, fp32) ----
// Block: 256 threads (tx 0..15, ty 0..15), BM = 64 rows, full K in smem.
template <int NOUT>
__device__ __forceinline__ void gemm_dual_body(float* sm,
                                               const float* __restrict__ A,
                                               const float* __restrict__ B1,
                                               const float* __restrict__ B2,
                                               float* __restrict__ C1,
                                               float* __restrict__ C2,
                                               int M) {
    float* Bs = sm;                       // [128][2*NOUT]
    float* As = sm + 128 * 2 * NOUT;      // [64][132] padded
    const int tid = threadIdx.x;
    const int tx = tid & 15;
    const int ty = tid >> 4;
    const int row0 = blockIdx.x * 64;
    constexpr int BCOLS = 2 * NOUT;
    constexpr int NJ = BCOLS / 64;        // float4 groups per thread

    // load both weight matrices into smem
    const int BTOT = 128 * BCOLS;
    for (int i = tid * 4; i < BTOT; i += 256 * 4) {
        int k = i / BCOLS;
        int c = i - k * BCOLS;
        float4 v;
        if (c < NOUT) v = *reinterpret_cast<const float4*>(B1 + k * NOUT + c);
        else          v = *reinterpret_cast<const float4*>(B2 + k * NOUT + (c - NOUT));
        *reinterpret_cast<float4*>(Bs + i) = v;
    }
    // load A tile (64 rows x 128) with padded stride 132
    for (int i = tid * 4; i < 64 * 128; i += 256 * 4) {
        int r = i >> 7;
        int c = i & 127;
        int gr = row0 + r;
        float4 v = make_float4(0.f, 0.f, 0.f, 0.f);
        if (gr < M) v = *reinterpret_cast<const float4*>(A + (size_t)gr * 128 + c);
        float* dst = As + r * 132 + c;
        dst[0] = v.x; dst[1] = v.y; dst[2] = v.z; dst[3] = v.w;
    }
    __syncthreads();

    float acc[4][NJ * 4];
#pragma unroll
    for (int r = 0; r < 4; r++)
#pragma unroll
        for (int c = 0; c < NJ * 4; c++) acc[r][c] = 0.f;

    for (int k = 0; k < 128; k++) {
        float a[4];
#pragma unroll
        for (int r = 0; r < 4; r++) a[r] = As[(ty * 4 + r) * 132 + k];
#pragma unroll
        for (int j = 0; j < NJ; j++) {
            float4 b = *reinterpret_cast<const float4*>(Bs + k * BCOLS + j * 64 + tx * 4);
#pragma unroll
            for (int r = 0; r < 4; r++) {
                acc[r][j * 4 + 0] += a[r] * b.x;
                acc[r][j * 4 + 1] += a[r] * b.y;
                acc[r][j * 4 + 2] += a[r] * b.z;
                acc[r][j * 4 + 3] += a[r] * b.w;
            }
        }
    }

#pragma unroll
    for (int r = 0; r < 4; r++) {
        int gr = row0 + ty * 4 + r;
        if (gr >= M) continue;
#pragma unroll
        for (int j = 0; j < NJ; j++) {
            int col = j * 64 + tx * 4;
            float4 v = make_float4(acc[r][j * 4 + 0], acc[r][j * 4 + 1],
                                   acc[r][j * 4 + 2], acc[r][j * 4 + 3]);
            if (col < NOUT)
                *reinterpret_cast<float4*>(C1 + (size_t)gr * NOUT + col) = v;
            else
                *reinterpret_cast<float4*>(C2 + (size_t)gr * NOUT + (col - NOUT)) = v;
        }
    }
}

__global__ void gemm1_kernel(const float* __restrict__ x,
                             const float* __restrict__ B1,
                             const float* __restrict__ B2) {
    extern __shared__ float sm[];
    gemm_dual_body<128>(sm, x, B1, B2, g_xl, g_xr, NN);
}

__global__ void gemm2_kernel(const float* __restrict__ B1,
                             const float* __restrict__ B2) {
    extern __shared__ float sm[];
    gemm_dual_body<64>(sm, g_h, B1, B2, g_hl, g_hr, NN);
}

// ---------------- vector reduction helper ---------------------------------
__device__ __forceinline__ void red_add_v4(float* p, float4 v) {
    asm volatile("red.global.add.v4.f32 [%0], {%1, %2, %3, %4};"
                 :: "l"(p), "f"(v.x), "f"(v.y), "f"(v.z), "f"(v.w)
                 : "memory");
}

// ---------------- scatter: g_agg[dst] += g_xl[src], 128-d (warp/edge) -----
__global__ void scatter128() {
    int lane = threadIdx.x & 31;
    int warp = (blockIdx.x * blockDim.x + threadIdx.x) >> 5;
    int nwarps = (gridDim.x * blockDim.x) >> 5;
    for (int e = warp; e < EE; e += nwarps) {
        int s = g_src[e];
        int d = g_dst[e];
        float4 v = *reinterpret_cast<const float4*>(g_xl + (size_t)s * 128 + lane * 4);
        red_add_v4(g_agg + (size_t)d * 128 + lane * 4, v);
    }
}

// ---------------- scatter: g_agg2[dst] += g_hl[src], 64-d (16 thr/edge) ---
__global__ void scatter64() {
    int i = blockIdx.x * blockDim.x + threadIdx.x;
    int stride = gridDim.x * blockDim.x;
    const int total = EE * 16;
    for (int it = i; it < total; it += stride) {
        int e = it >> 4;
        int c = (it & 15) << 2;
        int s = g_src[e];
        int d = g_dst[e];
        float4 v = *reinterpret_cast<const float4*>(g_hl + (size_t)s * 64 + c);
        red_add_v4(g_agg2 + (size_t)d * 64 + c, v);
    }
}

// ---------------- h = relu(agg/cnt + b1 + xr) -----------------------------
__global__ void h_kernel(const float* __restrict__ b1) {
    int i = blockIdx.x * blockDim.x + threadIdx.x;
    int stride = gridDim.x * blockDim.x;
    const int total = NN * 32;  // float4 items
    for (int it = i; it < total; it += stride) {
        int row = it >> 5;
        int c = (it & 31) << 2;
        float inv = 1.0f / fmaxf(g_cnt[row], 1.0f);
        float4 a = *reinterpret_cast<const float4*>(g_agg + (size_t)row * 128 + c);
        float4 r = *reinterpret_cast<const float4*>(g_xr + (size_t)row * 128 + c);
        float4 bb = *reinterpret_cast<const float4*>(b1 + c);
        float4 o;
        o.x = fmaxf(a.x * inv + bb.x + r.x, 0.f);
        o.y = fmaxf(a.y * inv + bb.y + r.y, 0.f);
        o.z = fmaxf(a.z * inv + bb.z + r.z, 0.f);
        o.w = fmaxf(a.w * inv + bb.w + r.w, 0.f);
        *reinterpret_cast<float4*>(g_h + (size_t)row * 128 + c) = o;
    }
}

// ---------------- out = agg2/cnt + b2 + hr --------------------------------
__global__ void out_kernel(const float* __restrict__ b2, float* __restrict__ out) {
    int i = blockIdx.x * blockDim.x + threadIdx.x;
    int stride = gridDim.x * blockDim.x;
    const int total = NN * 16;  // float4 items
    for (int it = i; it < total; it += stride) {
        int row = it >> 4;
        int c = (it & 15) << 2;
        float inv = 1.0f / fmaxf(g_cnt[row], 1.0f);
        float4 a = *reinterpret_cast<const float4*>(g_agg2 + (size_t)row * 64 + c);
        float4 r = *reinterpret_cast<const float4*>(g_hr + (size_t)row * 64 + c);
        float4 bb = *reinterpret_cast<const float4*>(b2 + c);
        float4 o;
        o.x = a.x * inv + bb.x + r.x;
        o.y = a.y * inv + bb.y + r.y;
        o.z = a.z * inv + bb.z + r.z;
        o.w = a.w * inv + bb.w + r.w;
        *reinterpret_cast<float4*>(out + (size_t)row * 64 + c) = o;
    }
}

// ---------------- launch ---------------------------------------------------
extern "C" void kernel_launch(void* const* d_in, const int* in_sizes, int n_in,
                              void* d_out, int out_size) {
    const float* x    = (const float*)d_in[0];
    const void*  ei   = d_in[1];
    const float* W_l1 = (const float*)d_in[2];
    const float* W_r1 = (const float*)d_in[3];
    const float* b1   = (const float*)d_in[4];
    const float* W_l2 = (const float*)d_in[5];
    const float* W_r2 = (const float*)d_in[6];
    const float* b2   = (const float*)d_in[7];
    float* out = (float*)d_out;

    const int smem1 = (128 * 256 + 64 * 132) * 4;  // 164,864 B
    const int smem2 = (128 * 128 + 64 * 132) * 4;  //  99,328 B
    cudaFuncSetAttribute(gemm1_kernel, cudaFuncAttributeMaxDynamicSharedMemorySize, smem1);
    cudaFuncSetAttribute(gemm2_kernel, cudaFuncAttributeMaxDynamicSharedMemorySize, smem2);

    const int GB = (NN + 63) / 64;  // 1563 gemm blocks

    detect_kernel<<<1, 32>>>(ei);
    zero_kernel<<<2048, 256>>>();
    convert_kernel<<<2048, 256>>>(ei);
    gemm1_kernel<<<GB, 256, smem1>>>(x, W_l1, W_r1);
    scatter128<<<2048, 256>>>();
    h_kernel<<<(NN * 32 + 255) / 256, 256>>>(b1);
    gemm2_kernel<<<GB, 256, smem2>>>(W_l2, W_r2);
    scatter64<<<4096, 256>>>();
    out_kernel<<<(NN * 16 + 255) / 256, 256>>>(b2, out);
}

// round 4
// speedup vs baseline: 1.3944x; 1.3944x over previous
#include <cuda_runtime.h>
#include <cuda_bf16.h>
#include <cstdint>
#include <cstddef>

#define NN 100000
#define EE 1600000
#define D_IN 128
#define HID 128
#define D_OUT 64

// ---------------- scratch (device globals) ---------------------------------
__device__ float g_c1[(size_t)NN * 256];    // [xl | xr] combined, stride 256
__device__ float g_c2[(size_t)NN * 128];    // [hl | hr] combined, stride 128
__device__ float g_agg[(size_t)NN * HID];   // layer-1 neighbor sum
__device__ float g_agg2[(size_t)NN * D_OUT];// layer-2 neighbor sum
__device__ float g_cnt[NN];                 // in-degree
__device__ int   g_src[EE];
__device__ int   g_dst[EE];
__device__ int   g_is64;
__device__ __nv_bfloat16 g_ahi[(size_t)NN * 128];  // A operand split (x, then h)
__device__ __nv_bfloat16 g_alo[(size_t)NN * 128];
__device__ __nv_bfloat16 g_w1T_hi[256 * 128];      // [n][k] transposed W1 = [Wl1|Wr1]
__device__ __nv_bfloat16 g_w1T_lo[256 * 128];
__device__ __nv_bfloat16 g_w2T_hi[128 * 128];      // [n][k] transposed W2 = [Wl2|Wr2]
__device__ __nv_bfloat16 g_w2T_lo[128 * 128];

// ---------------- dtype detection -----------------------------------------
__global__ void detect_kernel(const void* __restrict__ ei_raw) {
    if (threadIdx.x == 0 && blockIdx.x == 0) {
        const long long* e64 = (const long long*)ei_raw;
        int ok = 1;
        for (int i = 0; i < 256; i++) {
            long long v = e64[i];
            if (v < 0 || v >= NN) { ok = 0; break; }
        }
        g_is64 = ok;
    }
}

// ---------------- zero scratch --------------------------------------------
__global__ void zero_kernel() {
    int i = blockIdx.x * blockDim.x + threadIdx.x;
    int stride = gridDim.x * blockDim.x;
    float4 z = make_float4(0.f, 0.f, 0.f, 0.f);
    float4* a1 = reinterpret_cast<float4*>(g_agg);
    float4* a2 = reinterpret_cast<float4*>(g_agg2);
    const int n1 = NN * HID / 4;
    const int n2 = NN * D_OUT / 4;
    for (int idx = i; idx < n1; idx += stride) a1[idx] = z;
    for (int idx = i; idx < n2; idx += stride) a2[idx] = z;
    for (int idx = i; idx < NN; idx += stride) g_cnt[idx] = 0.f;
}

// ---------------- convert edges + degree count ------------------------------
__global__ void convert_kernel(const void* __restrict__ ei_raw) {
    int i = blockIdx.x * blockDim.x + threadIdx.x;
    int stride = gridDim.x * blockDim.x;
    const int is64 = g_is64;
    if (is64) {
        const long long* e64 = (const long long*)ei_raw;
        for (int e = i; e < EE; e += stride) {
            int s = (int)e64[e];
            int d = (int)e64[(size_t)EE + e];
            s = min(max(s, 0), NN - 1);
            d = min(max(d, 0), NN - 1);
            g_src[e] = s; g_dst[e] = d;
            atomicAdd(&g_cnt[d], 1.0f);
        }
    } else {
        const int* e32 = (const int*)ei_raw;
        for (int e = i; e < EE; e += stride) {
            int s = e32[e];
            int d = e32[EE + e];
            s = min(max(s, 0), NN - 1);
            d = min(max(d, 0), NN - 1);
            g_src[e] = s; g_dst[e] = d;
            atomicAdd(&g_cnt[d], 1.0f);
        }
    }
}

// ---------------- split helpers --------------------------------------------
__device__ __forceinline__ void split2(float a, float b,
                                       __nv_bfloat162& hi, __nv_bfloat162& lo) {
    __nv_bfloat16 ha = __float2bfloat16_rn(a);
    __nv_bfloat16 hb = __float2bfloat16_rn(b);
    __nv_bfloat16 la = __float2bfloat16_rn(a - __bfloat162float(ha));
    __nv_bfloat16 lb = __float2bfloat16_rn(b - __bfloat162float(hb));
    hi = __nv_bfloat162(ha, hb);
    lo = __nv_bfloat162(la, lb);
}

// ---------------- x -> bf16 hi/lo ------------------------------------------
__global__ void xconvert_kernel(const float* __restrict__ x) {
    int i = blockIdx.x * blockDim.x + threadIdx.x;
    int stride = gridDim.x * blockDim.x;
    const int total = NN * 64;  // float2 items
    __nv_bfloat162* ohi = reinterpret_cast<__nv_bfloat162*>(g_ahi);
    __nv_bfloat162* olo = reinterpret_cast<__nv_bfloat162*>(g_alo);
    const float2* xin = reinterpret_cast<const float2*>(x);
    for (int it = i; it < total; it += stride) {
        float2 v = xin[it];
        __nv_bfloat162 hi, lo;
        split2(v.x, v.y, hi, lo);
        ohi[it] = hi; olo[it] = lo;
    }
}

// ---------------- weights -> transposed bf16 hi/lo --------------------------
__global__ void wconvert_kernel(const float* __restrict__ Wl1,
                                const float* __restrict__ Wr1,
                                const float* __restrict__ Wl2,
                                const float* __restrict__ Wr2) {
    int i = blockIdx.x * blockDim.x + threadIdx.x;
    int stride = gridDim.x * blockDim.x;
    // W1: 256 n x 128 k
    for (int idx = i; idx < 256 * 128; idx += stride) {
        int n = idx >> 7, k = idx & 127;
        float v = (n < 128) ? Wl1[k * 128 + n] : Wr1[k * 128 + (n - 128)];
        __nv_bfloat16 h = __float2bfloat16_rn(v);
        g_w1T_hi[idx] = h;
        g_w1T_lo[idx] = __float2bfloat16_rn(v - __bfloat162float(h));
    }
    // W2: 128 n x 128 k
    for (int idx = i; idx < 128 * 128; idx += stride) {
        int n = idx >> 7, k = idx & 127;
        float v = (n < 64) ? Wl2[k * 64 + n] : Wr2[k * 64 + (n - 64)];
        __nv_bfloat16 h = __float2bfloat16_rn(v);
        g_w2T_hi[idx] = h;
        g_w2T_lo[idx] = __float2bfloat16_rn(v - __bfloat162float(h));
    }
}

// ---------------- bf16 split MMA GEMM ---------------------------------------
// C[M][ldc], block tile 64 rows x 128 cols, K = 128 (4 chunks of 32).
// 256 threads = 8 warps as 2(m) x 4(n); warp tile 32x32.
__device__ __forceinline__ void mma16816(float* c, const uint32_t* a, const uint32_t* b) {
    asm volatile("mma.sync.aligned.m16n8k16.row.col.f32.bf16.bf16.f32 "
                 "{%0,%1,%2,%3}, {%4,%5,%6,%7}, {%8,%9}, {%0,%1,%2,%3};"
                 : "+f"(c[0]), "+f"(c[1]), "+f"(c[2]), "+f"(c[3])
                 : "r"(a[0]), "r"(a[1]), "r"(a[2]), "r"(a[3]),
                   "r"(b[0]), "r"(b[1]));
}

#define LDS_S 40  // smem row stride in elements (bank-conflict-free, 4B aligned)

__global__ void __launch_bounds__(256)
mma_gemm_kernel(const __nv_bfloat16* __restrict__ WThi,
                const __nv_bfloat16* __restrict__ WTlo,
                float* __restrict__ C, int M, int ldc) {
    __shared__ __nv_bfloat16 sAhi[64 * LDS_S];
    __shared__ __nv_bfloat16 sAlo[64 * LDS_S];
    __shared__ __nv_bfloat16 sBhi[128 * LDS_S];
    __shared__ __nv_bfloat16 sBlo[128 * LDS_S];

    const int tid = threadIdx.x;
    const int wid = tid >> 5;
    const int lane = tid & 31;
    const int g = lane >> 2;
    const int t = lane & 3;
    const int wm = wid & 1;   // 0..1
    const int wn = wid >> 1;  // 0..3
    const int row0 = blockIdx.x * 64;
    const int n0 = blockIdx.y * 128;

    float acc[2][4][4];
#pragma unroll
    for (int mt = 0; mt < 2; mt++)
#pragma unroll
        for (int nt = 0; nt < 4; nt++)
#pragma unroll
            for (int c = 0; c < 4; c++) acc[mt][nt][c] = 0.f;

    for (int kc = 0; kc < 4; kc++) {
        const int k0 = kc * 32;
        __syncthreads();
        // load A tile: 64 rows x 32 cols, one uint4 (8 bf16) per thread per array
        {
            int r = tid >> 2, q = tid & 3;
            int gr = row0 + r;
            uint4 vh = make_uint4(0, 0, 0, 0), vl = make_uint4(0, 0, 0, 0);
            if (gr < M) {
                size_t gi = (size_t)gr * 128 + k0 + q * 8;
                vh = *reinterpret_cast<const uint4*>(g_ahi + gi);
                vl = *reinterpret_cast<const uint4*>(g_alo + gi);
            }
            int si = r * LDS_S + q * 8;
            *reinterpret_cast<uint4*>(sAhi + si) = vh;
            *reinterpret_cast<uint4*>(sAlo + si) = vl;
        }
        // load B tile: 128 n-rows x 32 k-cols from transposed weights
        {
#pragma unroll
            for (int j = 0; j < 2; j++) {
                int idx = tid + j * 256;
                int n = idx >> 2, q = idx & 3;
                size_t gi = (size_t)(n0 + n) * 128 + k0 + q * 8;
                int si = n * LDS_S + q * 8;
                *reinterpret_cast<uint4*>(sBhi + si) =
                    *reinterpret_cast<const uint4*>(WThi + gi);
                *reinterpret_cast<uint4*>(sBlo + si) =
                    *reinterpret_cast<const uint4*>(WTlo + gi);
            }
        }
        __syncthreads();

#pragma unroll
        for (int ks = 0; ks < 32; ks += 16) {
            uint32_t a[2][2][4];  // [mtile][hi/lo][reg]
#pragma unroll
            for (int mt = 0; mt < 2; mt++) {
                int base = (wm * 32 + mt * 16 + g) * LDS_S + ks + t * 2;
                a[mt][0][0] = *reinterpret_cast<const uint32_t*>(sAhi + base);
                a[mt][0][1] = *reinterpret_cast<const uint32_t*>(sAhi + base + 8 * LDS_S);
                a[mt][0][2] = *reinterpret_cast<const uint32_t*>(sAhi + base + 8);
                a[mt][0][3] = *reinterpret_cast<const uint32_t*>(sAhi + base + 8 * LDS_S + 8);
                a[mt][1][0] = *reinterpret_cast<const uint32_t*>(sAlo + base);
                a[mt][1][1] = *reinterpret_cast<const uint32_t*>(sAlo + base + 8 * LDS_S);
                a[mt][1][2] = *reinterpret_cast<const uint32_t*>(sAlo + base + 8);
                a[mt][1][3] = *reinterpret_cast<const uint32_t*>(sAlo + base + 8 * LDS_S + 8);
            }
            uint32_t b[4][2][2];  // [ntile][hi/lo][reg]
#pragma unroll
            for (int nt = 0; nt < 4; nt++) {
                int base = (wn * 32 + nt * 8 + g) * LDS_S + ks + t * 2;
                b[nt][0][0] = *reinterpret_cast<const uint32_t*>(sBhi + base);
                b[nt][0][1] = *reinterpret_cast<const uint32_t*>(sBhi + base + 8);
                b[nt][1][0] = *reinterpret_cast<const uint32_t*>(sBlo + base);
                b[nt][1][1] = *reinterpret_cast<const uint32_t*>(sBlo + base + 8);
            }
#pragma unroll
            for (int mt = 0; mt < 2; mt++)
#pragma unroll
                for (int nt = 0; nt < 4; nt++) {
                    mma16816(acc[mt][nt], a[mt][0], b[nt][0]);  // hi*hi
                    mma16816(acc[mt][nt], a[mt][0], b[nt][1]);  // hi*lo
                    mma16816(acc[mt][nt], a[mt][1], b[nt][0]);  // lo*hi
                }
        }
    }

    // epilogue
#pragma unroll
    for (int mt = 0; mt < 2; mt++) {
        int row = row0 + wm * 32 + mt * 16 + g;
#pragma unroll
        for (int nt = 0; nt < 4; nt++) {
            int col = n0 + wn * 32 + nt * 8 + t * 2;
            if (row < M)
                *reinterpret_cast<float2*>(C + (size_t)row * ldc + col) =
                    make_float2(acc[mt][nt][0], acc[mt][nt][1]);
            if (row + 8 < M)
                *reinterpret_cast<float2*>(C + (size_t)(row + 8) * ldc + col) =
                    make_float2(acc[mt][nt][2], acc[mt][nt][3]);
        }
    }
}

// ---------------- vector reduction helper ---------------------------------
__device__ __forceinline__ void red_add_v4(float* p, float4 v) {
    asm volatile("red.global.add.v4.f32 [%0], {%1, %2, %3, %4};"
                 :: "l"(p), "f"(v.x), "f"(v.y), "f"(v.z), "f"(v.w)
                 : "memory");
}

// ---------------- scatter: g_agg[dst] += c1[src][0:128], warp/edge --------
__global__ void scatter128() {
    int lane = threadIdx.x & 31;
    int warp = (blockIdx.x * blockDim.x + threadIdx.x) >> 5;
    int nwarps = (gridDim.x * blockDim.x) >> 5;
    for (int e = warp; e < EE; e += nwarps) {
        int s = g_src[e];
        int d = g_dst[e];
        float4 v = *reinterpret_cast<const float4*>(g_c1 + (size_t)s * 256 + lane * 4);
        red_add_v4(g_agg + (size_t)d * 128 + lane * 4, v);
    }
}

// ---------------- scatter: g_agg2[dst] += c2[src][0:64], 16 thr/edge ------
__global__ void scatter64() {
    int i = blockIdx.x * blockDim.x + threadIdx.x;
    int stride = gridDim.x * blockDim.x;
    const int total = EE * 16;
    for (int it = i; it < total; it += stride) {
        int e = it >> 4;
        int c = (it & 15) << 2;
        int s = g_src[e];
        int d = g_dst[e];
        float4 v = *reinterpret_cast<const float4*>(g_c2 + (size_t)s * 128 + c);
        red_add_v4(g_agg2 + (size_t)d * 64 + c, v);
    }
}

// ---------------- h = relu(agg/cnt + b1 + xr); write bf16 split ------------
__global__ void h_kernel(const float* __restrict__ b1) {
    int i = blockIdx.x * blockDim.x + threadIdx.x;
    int stride = gridDim.x * blockDim.x;
    const int total = NN * 64;  // float2 items
    __nv_bfloat162* ohi = reinterpret_cast<__nv_bfloat162*>(g_ahi);
    __nv_bfloat162* olo = reinterpret_cast<__nv_bfloat162*>(g_alo);
    for (int it = i; it < total; it += stride) {
        int row = it >> 6;
        int c = (it & 63) << 1;
        float inv = 1.0f / fmaxf(g_cnt[row], 1.0f);
        float2 a = *reinterpret_cast<const float2*>(g_agg + (size_t)row * 128 + c);
        float2 r = *reinterpret_cast<const float2*>(g_c1 + (size_t)row * 256 + 128 + c);
        float2 bb = *reinterpret_cast<const float2*>(b1 + c);
        float hx = fmaxf(a.x * inv + bb.x + r.x, 0.f);
        float hy = fmaxf(a.y * inv + bb.y + r.y, 0.f);
        __nv_bfloat162 hi, lo;
        split2(hx, hy, hi, lo);
        ohi[it] = hi; olo[it] = lo;
    }
}

// ---------------- out = agg2/cnt + b2 + hr --------------------------------
__global__ void out_kernel(const float* __restrict__ b2, float* __restrict__ out) {
    int i = blockIdx.x * blockDim.x + threadIdx.x;
    int stride = gridDim.x * blockDim.x;
    const int total = NN * 16;  // float4 items
    for (int it = i; it < total; it += stride) {
        int row = it >> 4;
        int c = (it & 15) << 2;
        float inv = 1.0f / fmaxf(g_cnt[row], 1.0f);
        float4 a = *reinterpret_cast<const float4*>(g_agg2 + (size_t)row * 64 + c);
        float4 r = *reinterpret_cast<const float4*>(g_c2 + (size_t)row * 128 + 64 + c);
        float4 bb = *reinterpret_cast<const float4*>(b2 + c);
        float4 o;
        o.x = a.x * inv + bb.x + r.x;
        o.y = a.y * inv + bb.y + r.y;
        o.z = a.z * inv + bb.z + r.z;
        o.w = a.w * inv + bb.w + r.w;
        *reinterpret_cast<float4*>(out + (size_t)row * 64 + c) = o;
    }
}

// ---------------- launch ---------------------------------------------------
extern "C" void kernel_launch(void* const* d_in, const int* in_sizes, int n_in,
                              void* d_out, int out_size) {
    const float* x    = (const float*)d_in[0];
    const void*  ei   = d_in[1];
    const float* W_l1 = (const float*)d_in[2];
    const float* W_r1 = (const float*)d_in[3];
    const float* b1   = (const float*)d_in[4];
    const float* W_l2 = (const float*)d_in[5];
    const float* W_r2 = (const float*)d_in[6];
    const float* b2   = (const float*)d_in[7];
    float* out = (float*)d_out;

    const int GB = (NN + 63) / 64;  // 1563 row tiles

    __nv_bfloat16 *w1hi, *w1lo, *w2hi, *w2lo;
    float *c1, *c2;
    cudaGetSymbolAddress((void**)&w1hi, g_w1T_hi);
    cudaGetSymbolAddress((void**)&w1lo, g_w1T_lo);
    cudaGetSymbolAddress((void**)&w2hi, g_w2T_hi);
    cudaGetSymbolAddress((void**)&w2lo, g_w2T_lo);
    cudaGetSymbolAddress((void**)&c1, g_c1);
    cudaGetSymbolAddress((void**)&c2, g_c2);

    detect_kernel<<<1, 32>>>(ei);
    zero_kernel<<<2048, 256>>>();
    convert_kernel<<<2048, 256>>>(ei);
    wconvert_kernel<<<64, 256>>>(W_l1, W_r1, W_l2, W_r2);
    xconvert_kernel<<<2048, 256>>>(x);
    mma_gemm_kernel<<<dim3(GB, 2), 256>>>(w1hi, w1lo, c1, NN, 256);
    scatter128<<<2048, 256>>>();
    h_kernel<<<(NN * 64 + 255) / 256, 256>>>(b1);
    mma_gemm_kernel<<<dim3(GB, 1), 256>>>(w2hi, w2lo, c2, NN, 128);
    scatter64<<<4096, 256>>>();
    out_kernel<<<(NN * 16 + 255) / 256, 256>>>(b2, out);
}

// round 5
// speedup vs baseline: 2.2160x; 1.5892x over previous
#include <cuda_runtime.h>
#include <cuda_bf16.h>
#include <cstdint>
#include <cstddef>

#define NN 100000
#define EE 1600000
#define D_IN 128
#define HID 128
#define D_OUT 64
#define NBLK 98  // ceil(NN/1024)

// ---------------- scratch (device globals) ---------------------------------
__device__ float g_c1[(size_t)NN * 256];    // [xl | xr] combined, stride 256
__device__ float g_c2[(size_t)NN * 128];    // [hl | hr] combined, stride 128
__device__ int   g_deg[NN];                 // in-degree
__device__ int   g_rowptr[NN + 1];          // CSR row offsets
__device__ int   g_cursor[NN];              // binning cursors
__device__ int   g_csr[EE];                 // CSR source list (grouped by dst)
__device__ int   g_blksum[128];             // scan block sums
__device__ int   g_is64;
__device__ __nv_bfloat16 g_ahi[(size_t)NN * 128];  // A operand split (x, then h)
__device__ __nv_bfloat16 g_alo[(size_t)NN * 128];
__device__ __nv_bfloat16 g_w1T_hi[256 * 128];      // [n][k] W1 = [Wl1|Wr1]^T
__device__ __nv_bfloat16 g_w1T_lo[256 * 128];
__device__ __nv_bfloat16 g_w2T_hi[128 * 128];      // [n][k] W2 = [Wl2|Wr2]^T
__device__ __nv_bfloat16 g_w2T_lo[128 * 128];

// ---------------- dtype detection + degree zero -----------------------------
__global__ void detect_kernel(const void* __restrict__ ei_raw) {
    if (threadIdx.x == 0 && blockIdx.x == 0) {
        const long long* e64 = (const long long*)ei_raw;
        int ok = 1;
        for (int i = 0; i < 256; i++) {
            long long v = e64[i];
            if (v < 0 || v >= NN) { ok = 0; break; }
        }
        g_is64 = ok;
    }
}

__global__ void zero_deg_kernel() {
    int i = blockIdx.x * blockDim.x + threadIdx.x;
    if (i < NN) g_deg[i] = 0;
}

// ---------------- degree count ----------------------------------------------
__global__ void count_kernel(const void* __restrict__ ei_raw) {
    int i = blockIdx.x * blockDim.x + threadIdx.x;
    int stride = gridDim.x * blockDim.x;
    if (g_is64) {
        const long long* e64 = (const long long*)ei_raw;
        for (int e = i; e < EE; e += stride) {
            int d = (int)e64[(size_t)EE + e];
            d = min(max(d, 0), NN - 1);
            atomicAdd(&g_deg[d], 1);
        }
    } else {
        const int* e32 = (const int*)ei_raw;
        for (int e = i; e < EE; e += stride) {
            int d = e32[EE + e];
            d = min(max(d, 0), NN - 1);
            atomicAdd(&g_deg[d], 1);
        }
    }
}

// ---------------- prefix scan (3 stages) ------------------------------------
__global__ void scan1_kernel() {
    __shared__ int sm[1024];
    int gi = blockIdx.x * 1024 + threadIdx.x;
    int v = (gi < NN) ? g_deg[gi] : 0;
    sm[threadIdx.x] = v;
    __syncthreads();
    for (int off = 1; off < 1024; off <<= 1) {
        int t = (threadIdx.x >= off) ? sm[threadIdx.x - off] : 0;
        __syncthreads();
        sm[threadIdx.x] += t;
        __syncthreads();
    }
    if (gi < NN) g_rowptr[gi] = sm[threadIdx.x] - v;  // exclusive
    if (threadIdx.x == 1023) g_blksum[blockIdx.x] = sm[1023];
}

__global__ void scan2_kernel() {
    if (threadIdx.x == 0 && blockIdx.x == 0) {
        int acc = 0;
        for (int i = 0; i < NBLK; i++) {
            int t = g_blksum[i];
            g_blksum[i] = acc;
            acc += t;
        }
    }
}

__global__ void scan3_kernel() {
    int gi = blockIdx.x * 1024 + threadIdx.x;
    if (gi < NN) {
        int v = g_rowptr[gi] + g_blksum[gi >> 10];
        g_rowptr[gi] = v;
        g_cursor[gi] = v;
    }
    if (gi == 0) g_rowptr[NN] = EE;
}

// ---------------- CSR binning ----------------------------------------------
__global__ void bin_kernel(const void* __restrict__ ei_raw) {
    int i = blockIdx.x * blockDim.x + threadIdx.x;
    int stride = gridDim.x * blockDim.x;
    if (g_is64) {
        const long long* e64 = (const long long*)ei_raw;
        for (int e = i; e < EE; e += stride) {
            int s = (int)e64[e];
            int d = (int)e64[(size_t)EE + e];
            s = min(max(s, 0), NN - 1);
            d = min(max(d, 0), NN - 1);
            int pos = atomicAdd(&g_cursor[d], 1);
            g_csr[pos] = s;
        }
    } else {
        const int* e32 = (const int*)ei_raw;
        for (int e = i; e < EE; e += stride) {
            int s = e32[e];
            int d = e32[EE + e];
            s = min(max(s, 0), NN - 1);
            d = min(max(d, 0), NN - 1);
            int pos = atomicAdd(&g_cursor[d], 1);
            g_csr[pos] = s;
        }
    }
}

// ---------------- split helpers --------------------------------------------
__device__ __forceinline__ void split2(float a, float b,
                                       __nv_bfloat162& hi, __nv_bfloat162& lo) {
    __nv_bfloat16 ha = __float2bfloat16_rn(a);
    __nv_bfloat16 hb = __float2bfloat16_rn(b);
    __nv_bfloat16 la = __float2bfloat16_rn(a - __bfloat162float(ha));
    __nv_bfloat16 lb = __float2bfloat16_rn(b - __bfloat162float(hb));
    hi = __nv_bfloat162(ha, hb);
    lo = __nv_bfloat162(la, lb);
}

// ---------------- x -> bf16 hi/lo ------------------------------------------
__global__ void xconvert_kernel(const float* __restrict__ x) {
    int i = blockIdx.x * blockDim.x + threadIdx.x;
    int stride = gridDim.x * blockDim.x;
    const int total = NN * 64;  // float2 items
    __nv_bfloat162* ohi = reinterpret_cast<__nv_bfloat162*>(g_ahi);
    __nv_bfloat162* olo = reinterpret_cast<__nv_bfloat162*>(g_alo);
    const float2* xin = reinterpret_cast<const float2*>(x);
    for (int it = i; it < total; it += stride) {
        float2 v = xin[it];
        __nv_bfloat162 hi, lo;
        split2(v.x, v.y, hi, lo);
        ohi[it] = hi; olo[it] = lo;
    }
}

// ---------------- weights -> transposed bf16 hi/lo --------------------------
__global__ void wconvert_kernel(const float* __restrict__ Wl1,
                                const float* __restrict__ Wr1,
                                const float* __restrict__ Wl2,
                                const float* __restrict__ Wr2) {
    int i = blockIdx.x * blockDim.x + threadIdx.x;
    int stride = gridDim.x * blockDim.x;
    for (int idx = i; idx < 256 * 128; idx += stride) {
        int n = idx >> 7, k = idx & 127;
        float v = (n < 128) ? Wl1[k * 128 + n] : Wr1[k * 128 + (n - 128)];
        __nv_bfloat16 h = __float2bfloat16_rn(v);
        g_w1T_hi[idx] = h;
        g_w1T_lo[idx] = __float2bfloat16_rn(v - __bfloat162float(h));
    }
    for (int idx = i; idx < 128 * 128; idx += stride) {
        int n = idx >> 7, k = idx & 127;
        float v = (n < 64) ? Wl2[k * 64 + n] : Wr2[k * 64 + (n - 64)];
        __nv_bfloat16 h = __float2bfloat16_rn(v);
        g_w2T_hi[idx] = h;
        g_w2T_lo[idx] = __float2bfloat16_rn(v - __bfloat162float(h));
    }
}

// ---------------- bf16 split MMA GEMM ---------------------------------------
__device__ __forceinline__ void mma16816(float* c, const uint32_t* a, const uint32_t* b) {
    asm volatile("mma.sync.aligned.m16n8k16.row.col.f32.bf16.bf16.f32 "
                 "{%0,%1,%2,%3}, {%4,%5,%6,%7}, {%8,%9}, {%0,%1,%2,%3};"
                 : "+f"(c[0]), "+f"(c[1]), "+f"(c[2]), "+f"(c[3])
                 : "r"(a[0]), "r"(a[1]), "r"(a[2]), "r"(a[3]),
                   "r"(b[0]), "r"(b[1]));
}

#define LDS_S 40

__global__ void __launch_bounds__(256)
mma_gemm_kernel(const __nv_bfloat16* __restrict__ WThi,
                const __nv_bfloat16* __restrict__ WTlo,
                float* __restrict__ C, int M, int ldc) {
    __shared__ __nv_bfloat16 sAhi[64 * LDS_S];
    __shared__ __nv_bfloat16 sAlo[64 * LDS_S];
    __shared__ __nv_bfloat16 sBhi[128 * LDS_S];
    __shared__ __nv_bfloat16 sBlo[128 * LDS_S];

    const int tid = threadIdx.x;
    const int wid = tid >> 5;
    const int lane = tid & 31;
    const int g = lane >> 2;
    const int t = lane & 3;
    const int wm = wid & 1;
    const int wn = wid >> 1;
    const int row0 = blockIdx.x * 64;
    const int n0 = blockIdx.y * 128;

    float acc[2][4][4];
#pragma unroll
    for (int mt = 0; mt < 2; mt++)
#pragma unroll
        for (int nt = 0; nt < 4; nt++)
#pragma unroll
            for (int c = 0; c < 4; c++) acc[mt][nt][c] = 0.f;

    for (int kc = 0; kc < 4; kc++) {
        const int k0 = kc * 32;
        __syncthreads();
        {
            int r = tid >> 2, q = tid & 3;
            int gr = row0 + r;
            uint4 vh = make_uint4(0, 0, 0, 0), vl = make_uint4(0, 0, 0, 0);
            if (gr < M) {
                size_t gi = (size_t)gr * 128 + k0 + q * 8;
                vh = *reinterpret_cast<const uint4*>(g_ahi + gi);
                vl = *reinterpret_cast<const uint4*>(g_alo + gi);
            }
            int si = r * LDS_S + q * 8;
            *reinterpret_cast<uint4*>(sAhi + si) = vh;
            *reinterpret_cast<uint4*>(sAlo + si) = vl;
        }
        {
#pragma unroll
            for (int j = 0; j < 2; j++) {
                int idx = tid + j * 256;
                int n = idx >> 2, q = idx & 3;
                size_t gi = (size_t)(n0 + n) * 128 + k0 + q * 8;
                int si = n * LDS_S + q * 8;
                *reinterpret_cast<uint4*>(sBhi + si) =
                    *reinterpret_cast<const uint4*>(WThi + gi);
                *reinterpret_cast<uint4*>(sBlo + si) =
                    *reinterpret_cast<const uint4*>(WTlo + gi);
            }
        }
        __syncthreads();

#pragma unroll
        for (int ks = 0; ks < 32; ks += 16) {
            uint32_t a[2][2][4];
#pragma unroll
            for (int mt = 0; mt < 2; mt++) {
                int base = (wm * 32 + mt * 16 + g) * LDS_S + ks + t * 2;
                a[mt][0][0] = *reinterpret_cast<const uint32_t*>(sAhi + base);
                a[mt][0][1] = *reinterpret_cast<const uint32_t*>(sAhi + base + 8 * LDS_S);
                a[mt][0][2] = *reinterpret_cast<const uint32_t*>(sAhi + base + 8);
                a[mt][0][3] = *reinterpret_cast<const uint32_t*>(sAhi + base + 8 * LDS_S + 8);
                a[mt][1][0] = *reinterpret_cast<const uint32_t*>(sAlo + base);
                a[mt][1][1] = *reinterpret_cast<const uint32_t*>(sAlo + base + 8 * LDS_S);
                a[mt][1][2] = *reinterpret_cast<const uint32_t*>(sAlo + base + 8);
                a[mt][1][3] = *reinterpret_cast<const uint32_t*>(sAlo + base + 8 * LDS_S + 8);
            }
            uint32_t b[4][2][2];
#pragma unroll
            for (int nt = 0; nt < 4; nt++) {
                int base = (wn * 32 + nt * 8 + g) * LDS_S + ks + t * 2;
                b[nt][0][0] = *reinterpret_cast<const uint32_t*>(sBhi + base);
                b[nt][0][1] = *reinterpret_cast<const uint32_t*>(sBhi + base + 8);
                b[nt][1][0] = *reinterpret_cast<const uint32_t*>(sBlo + base);
                b[nt][1][1] = *reinterpret_cast<const uint32_t*>(sBlo + base + 8);
            }
#pragma unroll
            for (int mt = 0; mt < 2; mt++)
#pragma unroll
                for (int nt = 0; nt < 4; nt++) {
                    mma16816(acc[mt][nt], a[mt][0], b[nt][0]);
                    mma16816(acc[mt][nt], a[mt][0], b[nt][1]);
                    mma16816(acc[mt][nt], a[mt][1], b[nt][0]);
                }
        }
    }

#pragma unroll
    for (int mt = 0; mt < 2; mt++) {
        int row = row0 + wm * 32 + mt * 16 + g;
#pragma unroll
        for (int nt = 0; nt < 4; nt++) {
            int col = n0 + wn * 32 + nt * 8 + t * 2;
            if (row < M)
                *reinterpret_cast<float2*>(C + (size_t)row * ldc + col) =
                    make_float2(acc[mt][nt][0], acc[mt][nt][1]);
            if (row + 8 < M)
                *reinterpret_cast<float2*>(C + (size_t)(row + 8) * ldc + col) =
                    make_float2(acc[mt][nt][2], acc[mt][nt][3]);
        }
    }
}

// ---------------- gather layer 1: warp/node, fused epilogue ----------------
// h = relu(mean_{s in N(w)} xl[s] + b1 + xr[w]); write bf16 hi/lo split.
__global__ void __launch_bounds__(256) gather1_kernel(const float* __restrict__ b1) {
    int w = (blockIdx.x * 256 + threadIdx.x) >> 5;
    if (w >= NN) return;
    int lane = threadIdx.x & 31;
    int beg = g_rowptr[w], end = g_rowptr[w + 1];
    float4 a0 = make_float4(0.f, 0.f, 0.f, 0.f);
    float4 a1 = make_float4(0.f, 0.f, 0.f, 0.f);
    int j = beg;
    for (; j + 2 <= end; j += 2) {
        int s0 = g_csr[j], s1 = g_csr[j + 1];
        float4 v0 = *reinterpret_cast<const float4*>(g_c1 + (size_t)s0 * 256 + lane * 4);
        float4 v1 = *reinterpret_cast<const float4*>(g_c1 + (size_t)s1 * 256 + lane * 4);
        a0.x += v0.x; a0.y += v0.y; a0.z += v0.z; a0.w += v0.w;
        a1.x += v1.x; a1.y += v1.y; a1.z += v1.z; a1.w += v1.w;
    }
    if (j < end) {
        int s0 = g_csr[j];
        float4 v0 = *reinterpret_cast<const float4*>(g_c1 + (size_t)s0 * 256 + lane * 4);
        a0.x += v0.x; a0.y += v0.y; a0.z += v0.z; a0.w += v0.w;
    }
    float inv = 1.0f / fmaxf((float)(end - beg), 1.0f);
    float4 r = *reinterpret_cast<const float4*>(g_c1 + (size_t)w * 256 + 128 + lane * 4);
    float4 bb = *reinterpret_cast<const float4*>(b1 + lane * 4);
    float h0 = fmaxf((a0.x + a1.x) * inv + bb.x + r.x, 0.f);
    float h1 = fmaxf((a0.y + a1.y) * inv + bb.y + r.y, 0.f);
    float h2 = fmaxf((a0.z + a1.z) * inv + bb.z + r.z, 0.f);
    float h3 = fmaxf((a0.w + a1.w) * inv + bb.w + r.w, 0.f);
    __nv_bfloat162 hi0, lo0, hi1, lo1;
    split2(h0, h1, hi0, lo0);
    split2(h2, h3, hi1, lo1);
    size_t o = (size_t)w * 128 + lane * 4;
    uint2 ph = make_uint2(*reinterpret_cast<uint32_t*>(&hi0),
                          *reinterpret_cast<uint32_t*>(&hi1));
    uint2 pl = make_uint2(*reinterpret_cast<uint32_t*>(&lo0),
                          *reinterpret_cast<uint32_t*>(&lo1));
    *reinterpret_cast<uint2*>(g_ahi + o) = ph;
    *reinterpret_cast<uint2*>(g_alo + o) = pl;
}

// ---------------- gather layer 2: warp/node, fused epilogue ----------------
// out = mean_{s in N(w)} hl[s] + b2 + hr[w]
__global__ void __launch_bounds__(256) gather2_kernel(const float* __restrict__ b2,
                                                      float* __restrict__ out) {
    int w = (blockIdx.x * 256 + threadIdx.x) >> 5;
    if (w >= NN) return;
    int lane = threadIdx.x & 31;
    int beg = g_rowptr[w], end = g_rowptr[w + 1];
    float2 a0 = make_float2(0.f, 0.f);
    float2 a1 = make_float2(0.f, 0.f);
    int j = beg;
    for (; j + 2 <= end; j += 2) {
        int s0 = g_csr[j], s1 = g_csr[j + 1];
        float2 v0 = *reinterpret_cast<const float2*>(g_c2 + (size_t)s0 * 128 + lane * 2);
        float2 v1 = *reinterpret_cast<const float2*>(g_c2 + (size_t)s1 * 128 + lane * 2);
        a0.x += v0.x; a0.y += v0.y;
        a1.x += v1.x; a1.y += v1.y;
    }
    if (j < end) {
        int s0 = g_csr[j];
        float2 v0 = *reinterpret_cast<const float2*>(g_c2 + (size_t)s0 * 128 + lane * 2);
        a0.x += v0.x; a0.y += v0.y;
    }
    float inv = 1.0f / fmaxf((float)(end - beg), 1.0f);
    float2 r = *reinterpret_cast<const float2*>(g_c2 + (size_t)w * 128 + 64 + lane * 2);
    float2 bb = *reinterpret_cast<const float2*>(b2 + lane * 2);
    float2 o;
    o.x = (a0.x + a1.x) * inv + bb.x + r.x;
    o.y = (a0.y + a1.y) * inv + bb.y + r.y;
    *reinterpret_cast<float2*>(out + (size_t)w * 64 + lane * 2) = o;
}

// ---------------- launch ---------------------------------------------------
extern "C" void kernel_launch(void* const* d_in, const int* in_sizes, int n_in,
                              void* d_out, int out_size) {
    const float* x    = (const float*)d_in[0];
    const void*  ei   = d_in[1];
    const float* W_l1 = (const float*)d_in[2];
    const float* W_r1 = (const float*)d_in[3];
    const float* b1   = (const float*)d_in[4];
    const float* W_l2 = (const float*)d_in[5];
    const float* W_r2 = (const float*)d_in[6];
    const float* b2   = (const float*)d_in[7];
    float* out = (float*)d_out;

    const int GB = (NN + 63) / 64;        // 1563 row tiles
    const int GW = (NN * 32 + 255) / 256; // warp-per-node grid

    __nv_bfloat16 *w1hi, *w1lo, *w2hi, *w2lo;
    float *c1, *c2;
    cudaGetSymbolAddress((void**)&w1hi, g_w1T_hi);
    cudaGetSymbolAddress((void**)&w1lo, g_w1T_lo);
    cudaGetSymbolAddress((void**)&w2hi, g_w2T_hi);
    cudaGetSymbolAddress((void**)&w2lo, g_w2T_lo);
    cudaGetSymbolAddress((void**)&c1, g_c1);
    cudaGetSymbolAddress((void**)&c2, g_c2);

    detect_kernel<<<1, 32>>>(ei);
    zero_deg_kernel<<<NBLK, 1024>>>();
    count_kernel<<<2048, 256>>>(ei);
    scan1_kernel<<<NBLK, 1024>>>();
    scan2_kernel<<<1, 32>>>();
    scan3_kernel<<<NBLK, 1024>>>();
    bin_kernel<<<2048, 256>>>(ei);
    wconvert_kernel<<<256, 256>>>(W_l1, W_r1, W_l2, W_r2);
    xconvert_kernel<<<2048, 256>>>(x);
    mma_gemm_kernel<<<dim3(GB, 2), 256>>>(w1hi, w1lo, c1, NN, 256);
    gather1_kernel<<<GW, 256>>>(b1);
    mma_gemm_kernel<<<dim3(GB, 1), 256>>>(w2hi, w2lo, c2, NN, 128);
    gather2_kernel<<<GW, 256>>>(b2, out);
}

// round 6
// speedup vs baseline: 2.2162x; 1.0001x over previous
#include <cuda_runtime.h>
#include <cuda_bf16.h>
#include <cstdint>
#include <cstddef>

#define NN 100000
#define EE 1600000
#define D_IN 128
#define HID 128
#define D_OUT 64
#define NBLK 98  // ceil(NN/1024)

// ---------------- scratch (device globals) ---------------------------------
__device__ float g_c1[(size_t)NN * 256];    // [xl | xr] combined, stride 256
__device__ float g_c2[(size_t)NN * 128];    // [hl | hr] combined, stride 128
__device__ int   g_deg[NN];                 // in-degree
__device__ int   g_rowptr[NN + 1];          // CSR row offsets
__device__ int   g_cursor[NN];              // binning cursors
__device__ int   g_csr[EE];                 // CSR source list (grouped by dst)
__device__ int   g_blksum[128];             // scan block sums
__device__ int   g_is64;
__device__ __nv_bfloat16 g_ahi[(size_t)NN * 128];  // A operand split (x, then h)
__device__ __nv_bfloat16 g_alo[(size_t)NN * 128];
__device__ __nv_bfloat16 g_w1T_hi[256 * 128];      // [n][k] W1 = [Wl1|Wr1]^T
__device__ __nv_bfloat16 g_w1T_lo[256 * 128];
__device__ __nv_bfloat16 g_w2T_hi[128 * 128];      // [n][k] W2 = [Wl2|Wr2]^T
__device__ __nv_bfloat16 g_w2T_lo[128 * 128];

// ---------------- dtype detection + degree zero -----------------------------
__global__ void detect_kernel(const void* __restrict__ ei_raw) {
    if (threadIdx.x == 0 && blockIdx.x == 0) {
        const long long* e64 = (const long long*)ei_raw;
        int ok = 1;
        for (int i = 0; i < 256; i++) {
            long long v = e64[i];
            if (v < 0 || v >= NN) { ok = 0; break; }
        }
        g_is64 = ok;
    }
}

__global__ void zero_deg_kernel() {
    int i = blockIdx.x * blockDim.x + threadIdx.x;
    if (i < NN) g_deg[i] = 0;
}

// ---------------- degree count ----------------------------------------------
__global__ void count_kernel(const void* __restrict__ ei_raw) {
    int i = blockIdx.x * blockDim.x + threadIdx.x;
    int stride = gridDim.x * blockDim.x;
    if (g_is64) {
        const long long* e64 = (const long long*)ei_raw;
        for (int e = i; e < EE; e += stride) {
            int d = (int)e64[(size_t)EE + e];
            d = min(max(d, 0), NN - 1);
            atomicAdd(&g_deg[d], 1);
        }
    } else {
        const int* e32 = (const int*)ei_raw;
        for (int e = i; e < EE; e += stride) {
            int d = e32[EE + e];
            d = min(max(d, 0), NN - 1);
            atomicAdd(&g_deg[d], 1);
        }
    }
}

// ---------------- prefix scan (3 stages) ------------------------------------
__global__ void scan1_kernel() {
    __shared__ int sm[1024];
    int gi = blockIdx.x * 1024 + threadIdx.x;
    int v = (gi < NN) ? g_deg[gi] : 0;
    sm[threadIdx.x] = v;
    __syncthreads();
    for (int off = 1; off < 1024; off <<= 1) {
        int t = (threadIdx.x >= off) ? sm[threadIdx.x - off] : 0;
        __syncthreads();
        sm[threadIdx.x] += t;
        __syncthreads();
    }
    if (gi < NN) g_rowptr[gi] = sm[threadIdx.x] - v;  // exclusive
    if (threadIdx.x == 1023) g_blksum[blockIdx.x] = sm[1023];
}

__global__ void scan2_kernel() {
    if (threadIdx.x == 0 && blockIdx.x == 0) {
        int acc = 0;
        for (int i = 0; i < NBLK; i++) {
            int t = g_blksum[i];
            g_blksum[i] = acc;
            acc += t;
        }
    }
}

__global__ void scan3_kernel() {
    int gi = blockIdx.x * 1024 + threadIdx.x;
    if (gi < NN) {
        int v = g_rowptr[gi] + g_blksum[gi >> 10];
        g_rowptr[gi] = v;
        g_cursor[gi] = v;
    }
    if (gi == 0) g_rowptr[NN] = EE;
}

// ---------------- CSR binning ----------------------------------------------
__global__ void bin_kernel(const void* __restrict__ ei_raw) {
    int i = blockIdx.x * blockDim.x + threadIdx.x;
    int stride = gridDim.x * blockDim.x;
    if (g_is64) {
        const long long* e64 = (const long long*)ei_raw;
        for (int e = i; e < EE; e += stride) {
            int s = (int)e64[e];
            int d = (int)e64[(size_t)EE + e];
            s = min(max(s, 0), NN - 1);
            d = min(max(d, 0), NN - 1);
            int pos = atomicAdd(&g_cursor[d], 1);
            g_csr[pos] = s;
        }
    } else {
        const int* e32 = (const int*)ei_raw;
        for (int e = i; e < EE; e += stride) {
            int s = e32[e];
            int d = e32[EE + e];
            s = min(max(s, 0), NN - 1);
            d = min(max(d, 0), NN - 1);
            int pos = atomicAdd(&g_cursor[d], 1);
            g_csr[pos] = s;
        }
    }
}

// ---------------- split helpers --------------------------------------------
__device__ __forceinline__ void split2(float a, float b,
                                       __nv_bfloat162& hi, __nv_bfloat162& lo) {
    __nv_bfloat16 ha = __float2bfloat16_rn(a);
    __nv_bfloat16 hb = __float2bfloat16_rn(b);
    __nv_bfloat16 la = __float2bfloat16_rn(a - __bfloat162float(ha));
    __nv_bfloat16 lb = __float2bfloat16_rn(b - __bfloat162float(hb));
    hi = __nv_bfloat162(ha, hb);
    lo = __nv_bfloat162(la, lb);
}

// ---------------- x -> bf16 hi/lo ------------------------------------------
__global__ void xconvert_kernel(const float* __restrict__ x) {
    int i = blockIdx.x * blockDim.x + threadIdx.x;
    int stride = gridDim.x * blockDim.x;
    const int total = NN * 64;  // float2 items
    __nv_bfloat162* ohi = reinterpret_cast<__nv_bfloat162*>(g_ahi);
    __nv_bfloat162* olo = reinterpret_cast<__nv_bfloat162*>(g_alo);
    const float2* xin = reinterpret_cast<const float2*>(x);
    for (int it = i; it < total; it += stride) {
        float2 v = xin[it];
        __nv_bfloat162 hi, lo;
        split2(v.x, v.y, hi, lo);
        ohi[it] = hi; olo[it] = lo;
    }
}

// ---------------- weights -> transposed bf16 hi/lo --------------------------
__global__ void wconvert_kernel(const float* __restrict__ Wl1,
                                const float* __restrict__ Wr1,
                                const float* __restrict__ Wl2,
                                const float* __restrict__ Wr2) {
    int i = blockIdx.x * blockDim.x + threadIdx.x;
    int stride = gridDim.x * blockDim.x;
    for (int idx = i; idx < 256 * 128; idx += stride) {
        int n = idx >> 7, k = idx & 127;
        float v = (n < 128) ? Wl1[k * 128 + n] : Wr1[k * 128 + (n - 128)];
        __nv_bfloat16 h = __float2bfloat16_rn(v);
        g_w1T_hi[idx] = h;
        g_w1T_lo[idx] = __float2bfloat16_rn(v - __bfloat162float(h));
    }
    for (int idx = i; idx < 128 * 128; idx += stride) {
        int n = idx >> 7, k = idx & 127;
        float v = (n < 64) ? Wl2[k * 64 + n] : Wr2[k * 64 + (n - 64)];
        __nv_bfloat16 h = __float2bfloat16_rn(v);
        g_w2T_hi[idx] = h;
        g_w2T_lo[idx] = __float2bfloat16_rn(v - __bfloat162float(h));
    }
}

// ---------------- bf16 split MMA GEMM ---------------------------------------
__device__ __forceinline__ void mma16816(float* c, const uint32_t* a, const uint32_t* b) {
    asm volatile("mma.sync.aligned.m16n8k16.row.col.f32.bf16.bf16.f32 "
                 "{%0,%1,%2,%3}, {%4,%5,%6,%7}, {%8,%9}, {%0,%1,%2,%3};"
                 : "+f"(c[0]), "+f"(c[1]), "+f"(c[2]), "+f"(c[3])
                 : "r"(a[0]), "r"(a[1]), "r"(a[2]), "r"(a[3]),
                   "r"(b[0]), "r"(b[1]));
}

#define LDS_S 40

__global__ void __launch_bounds__(256)
mma_gemm_kernel(const __nv_bfloat16* __restrict__ WThi,
                const __nv_bfloat16* __restrict__ WTlo,
                float* __restrict__ C, int M, int ldc) {
    __shared__ __nv_bfloat16 sAhi[64 * LDS_S];
    __shared__ __nv_bfloat16 sAlo[64 * LDS_S];
    __shared__ __nv_bfloat16 sBhi[128 * LDS_S];
    __shared__ __nv_bfloat16 sBlo[128 * LDS_S];

    const int tid = threadIdx.x;
    const int wid = tid >> 5;
    const int lane = tid & 31;
    const int g = lane >> 2;
    const int t = lane & 3;
    const int wm = wid & 1;
    const int wn = wid >> 1;
    const int row0 = blockIdx.x * 64;
    const int n0 = blockIdx.y * 128;

    float acc[2][4][4];
#pragma unroll
    for (int mt = 0; mt < 2; mt++)
#pragma unroll
        for (int nt = 0; nt < 4; nt++)
#pragma unroll
            for (int c = 0; c < 4; c++) acc[mt][nt][c] = 0.f;

    for (int kc = 0; kc < 4; kc++) {
        const int k0 = kc * 32;
        __syncthreads();
        {
            int r = tid >> 2, q = tid & 3;
            int gr = row0 + r;
            uint4 vh = make_uint4(0, 0, 0, 0), vl = make_uint4(0, 0, 0, 0);
            if (gr < M) {
                size_t gi = (size_t)gr * 128 + k0 + q * 8;
                vh = *reinterpret_cast<const uint4*>(g_ahi + gi);
                vl = *reinterpret_cast<const uint4*>(g_alo + gi);
            }
            int si = r * LDS_S + q * 8;
            *reinterpret_cast<uint4*>(sAhi + si) = vh;
            *reinterpret_cast<uint4*>(sAlo + si) = vl;
        }
        {
#pragma unroll
            for (int j = 0; j < 2; j++) {
                int idx = tid + j * 256;
                int n = idx >> 2, q = idx & 3;
                size_t gi = (size_t)(n0 + n) * 128 + k0 + q * 8;
                int si = n * LDS_S + q * 8;
                *reinterpret_cast<uint4*>(sBhi + si) =
                    *reinterpret_cast<const uint4*>(WThi + gi);
                *reinterpret_cast<uint4*>(sBlo + si) =
                    *reinterpret_cast<const uint4*>(WTlo + gi);
            }
        }
        __syncthreads();

#pragma unroll
        for (int ks = 0; ks < 32; ks += 16) {
            uint32_t a[2][2][4];
#pragma unroll
            for (int mt = 0; mt < 2; mt++) {
                int base = (wm * 32 + mt * 16 + g) * LDS_S + ks + t * 2;
                a[mt][0][0] = *reinterpret_cast<const uint32_t*>(sAhi + base);
                a[mt][0][1] = *reinterpret_cast<const uint32_t*>(sAhi + base + 8 * LDS_S);
                a[mt][0][2] = *reinterpret_cast<const uint32_t*>(sAhi + base + 8);
                a[mt][0][3] = *reinterpret_cast<const uint32_t*>(sAhi + base + 8 * LDS_S + 8);
                a[mt][1][0] = *reinterpret_cast<const uint32_t*>(sAlo + base);
                a[mt][1][1] = *reinterpret_cast<const uint32_t*>(sAlo + base + 8 * LDS_S);
                a[mt][1][2] = *reinterpret_cast<const uint32_t*>(sAlo + base + 8);
                a[mt][1][3] = *reinterpret_cast<const uint32_t*>(sAlo + base + 8 * LDS_S + 8);
            }
            uint32_t b[4][2][2];
#pragma unroll
            for (int nt = 0; nt < 4; nt++) {
                int base = (wn * 32 + nt * 8 + g) * LDS_S + ks + t * 2;
                b[nt][0][0] = *reinterpret_cast<const uint32_t*>(sBhi + base);
                b[nt][0][1] = *reinterpret_cast<const uint32_t*>(sBhi + base + 8);
                b[nt][1][0] = *reinterpret_cast<const uint32_t*>(sBlo + base);
                b[nt][1][1] = *reinterpret_cast<const uint32_t*>(sBlo + base + 8);
            }
#pragma unroll
            for (int mt = 0; mt < 2; mt++)
#pragma unroll
                for (int nt = 0; nt < 4; nt++) {
                    mma16816(acc[mt][nt], a[mt][0], b[nt][0]);
                    mma16816(acc[mt][nt], a[mt][0], b[nt][1]);
                    mma16816(acc[mt][nt], a[mt][1], b[nt][0]);
                }
        }
    }

#pragma unroll
    for (int mt = 0; mt < 2; mt++) {
        int row = row0 + wm * 32 + mt * 16 + g;
#pragma unroll
        for (int nt = 0; nt < 4; nt++) {
            int col = n0 + wn * 32 + nt * 8 + t * 2;
            if (row < M)
                *reinterpret_cast<float2*>(C + (size_t)row * ldc + col) =
                    make_float2(acc[mt][nt][0], acc[mt][nt][1]);
            if (row + 8 < M)
                *reinterpret_cast<float2*>(C + (size_t)(row + 8) * ldc + col) =
                    make_float2(acc[mt][nt][2], acc[mt][nt][3]);
        }
    }
}

// ---------------- gather layer 1: warp/node, fused epilogue ----------------
// h = relu(mean_{s in N(w)} xl[s] + b1 + xr[w]); write bf16 hi/lo split.
__global__ void __launch_bounds__(256) gather1_kernel(const float* __restrict__ b1) {
    int w = (blockIdx.x * 256 + threadIdx.x) >> 5;
    if (w >= NN) return;
    int lane = threadIdx.x & 31;
    int beg = g_rowptr[w], end = g_rowptr[w + 1];
    float4 a0 = make_float4(0.f, 0.f, 0.f, 0.f);
    float4 a1 = make_float4(0.f, 0.f, 0.f, 0.f);
    int j = beg;
    for (; j + 2 <= end; j += 2) {
        int s0 = g_csr[j], s1 = g_csr[j + 1];
        float4 v0 = *reinterpret_cast<const float4*>(g_c1 + (size_t)s0 * 256 + lane * 4);
        float4 v1 = *reinterpret_cast<const float4*>(g_c1 + (size_t)s1 * 256 + lane * 4);
        a0.x += v0.x; a0.y += v0.y; a0.z += v0.z; a0.w += v0.w;
        a1.x += v1.x; a1.y += v1.y; a1.z += v1.z; a1.w += v1.w;
    }
    if (j < end) {
        int s0 = g_csr[j];
        float4 v0 = *reinterpret_cast<const float4*>(g_c1 + (size_t)s0 * 256 + lane * 4);
        a0.x += v0.x; a0.y += v0.y; a0.z += v0.z; a0.w += v0.w;
    }
    float inv = 1.0f / fmaxf((float)(end - beg), 1.0f);
    float4 r = *reinterpret_cast<const float4*>(g_c1 + (size_t)w * 256 + 128 + lane * 4);
    float4 bb = *reinterpret_cast<const float4*>(b1 + lane * 4);
    float h0 = fmaxf((a0.x + a1.x) * inv + bb.x + r.x, 0.f);
    float h1 = fmaxf((a0.y + a1.y) * inv + bb.y + r.y, 0.f);
    float h2 = fmaxf((a0.z + a1.z) * inv + bb.z + r.z, 0.f);
    float h3 = fmaxf((a0.w + a1.w) * inv + bb.w + r.w, 0.f);
    __nv_bfloat162 hi0, lo0, hi1, lo1;
    split2(h0, h1, hi0, lo0);
    split2(h2, h3, hi1, lo1);
    size_t o = (size_t)w * 128 + lane * 4;
    uint2 ph = make_uint2(*reinterpret_cast<uint32_t*>(&hi0),
                          *reinterpret_cast<uint32_t*>(&hi1));
    uint2 pl = make_uint2(*reinterpret_cast<uint32_t*>(&lo0),
                          *reinterpret_cast<uint32_t*>(&lo1));
    *reinterpret_cast<uint2*>(g_ahi + o) = ph;
    *reinterpret_cast<uint2*>(g_alo + o) = pl;
}

// ---------------- gather layer 2: warp/node, fused epilogue ----------------
// out = mean_{s in N(w)} hl[s] + b2 + hr[w]
__global__ void __launch_bounds__(256) gather2_kernel(const float* __restrict__ b2,
                                                      float* __restrict__ out) {
    int w = (blockIdx.x * 256 + threadIdx.x) >> 5;
    if (w >= NN) return;
    int lane = threadIdx.x & 31;
    int beg = g_rowptr[w], end = g_rowptr[w + 1];
    float2 a0 = make_float2(0.f, 0.f);
    float2 a1 = make_float2(0.f, 0.f);
    int j = beg;
    for (; j + 2 <= end; j += 2) {
        int s0 = g_csr[j], s1 = g_csr[j + 1];
        float2 v0 = *reinterpret_cast<const float2*>(g_c2 + (size_t)s0 * 128 + lane * 2);
        float2 v1 = *reinterpret_cast<const float2*>(g_c2 + (size_t)s1 * 128 + lane * 2);
        a0.x += v0.x; a0.y += v0.y;
        a1.x += v1.x; a1.y += v1.y;
    }
    if (j < end) {
        int s0 = g_csr[j];
        float2 v0 = *reinterpret_cast<const float2*>(g_c2 + (size_t)s0 * 128 + lane * 2);
        a0.x += v0.x; a0.y += v0.y;
    }
    float inv = 1.0f / fmaxf((float)(end - beg), 1.0f);
    float2 r = *reinterpret_cast<const float2*>(g_c2 + (size_t)w * 128 + 64 + lane * 2);
    float2 bb = *reinterpret_cast<const float2*>(b2 + lane * 2);
    float2 o;
    o.x = (a0.x + a1.x) * inv + bb.x + r.x;
    o.y = (a0.y + a1.y) * inv + bb.y + r.y;
    *reinterpret_cast<float2*>(out + (size_t)w * 64 + lane * 2) = o;
}

// ---------------- launch ---------------------------------------------------
extern "C" void kernel_launch(void* const* d_in, const int* in_sizes, int n_in,
                              void* d_out, int out_size) {
    const float* x    = (const float*)d_in[0];
    const void*  ei   = d_in[1];
    const float* W_l1 = (const float*)d_in[2];
    const float* W_r1 = (const float*)d_in[3];
    const float* b1   = (const float*)d_in[4];
    const float* W_l2 = (const float*)d_in[5];
    const float* W_r2 = (const float*)d_in[6];
    const float* b2   = (const float*)d_in[7];
    float* out = (float*)d_out;

    const int GB = (NN + 63) / 64;        // 1563 row tiles
    const int GW = (NN * 32 + 255) / 256; // warp-per-node grid

    __nv_bfloat16 *w1hi, *w1lo, *w2hi, *w2lo;
    float *c1, *c2;
    cudaGetSymbolAddress((void**)&w1hi, g_w1T_hi);
    cudaGetSymbolAddress((void**)&w1lo, g_w1T_lo);
    cudaGetSymbolAddress((void**)&w2hi, g_w2T_hi);
    cudaGetSymbolAddress((void**)&w2lo, g_w2T_lo);
    cudaGetSymbolAddress((void**)&c1, g_c1);
    cudaGetSymbolAddress((void**)&c2, g_c2);

    detect_kernel<<<1, 32>>>(ei);
    zero_deg_kernel<<<NBLK, 1024>>>();
    count_kernel<<<2048, 256>>>(ei);
    scan1_kernel<<<NBLK, 1024>>>();
    scan2_kernel<<<1, 32>>>();
    scan3_kernel<<<NBLK, 1024>>>();
    bin_kernel<<<2048, 256>>>(ei);
    wconvert_kernel<<<256, 256>>>(W_l1, W_r1, W_l2, W_r2);
    xconvert_kernel<<<2048, 256>>>(x);
    mma_gemm_kernel<<<dim3(GB, 2), 256>>>(w1hi, w1lo, c1, NN, 256);
    gather1_kernel<<<GW, 256>>>(b1);
    mma_gemm_kernel<<<dim3(GB, 1), 256>>>(w2hi, w2lo, c2, NN, 128);
    gather2_kernel<<<GW, 256>>>(b2, out);
}